// round 5
// baseline (speedup 1.0000x reference)
#include <cuda_runtime.h>

#define NUM_USERS 100000
#define NUM_ITEMS 50000
#define N_NODES   150000
#define DIM       64
#define NUM_EDGES 4000000

// Scratch (allocation-free rule: __device__ globals).
__device__ float g_bufA[N_NODES * DIM];
__device__ float g_bufB[N_NODES * DIM];
__device__ int2  g_edges[NUM_EDGES];       // interleaved {col, val-bits}
__device__ int   g_hist[N_NODES];
__device__ int   g_rowptr[N_NODES + 1];
__device__ int   g_cursor[N_NODES];

// -------------------------------------------------------------------------
// Kernel 1: zero histogram.
// -------------------------------------------------------------------------
__global__ void lgcn_zero_hist()
{
    int i = blockIdx.x * blockDim.x + threadIdx.x;
    if (i < N_NODES) g_hist[i] = 0;
}

// -------------------------------------------------------------------------
// Kernel 2: degree histogram, 8 edges/thread (2x int4 loads).
// -------------------------------------------------------------------------
__global__ void lgcn_hist(const int* __restrict__ edge_row)
{
    int i = blockIdx.x * blockDim.x + threadIdx.x;
    if (i >= NUM_EDGES / 8) return;
    int4 r0 = ((const int4*)edge_row)[i * 2];
    int4 r1 = ((const int4*)edge_row)[i * 2 + 1];
    atomicAdd(&g_hist[r0.x], 1);
    atomicAdd(&g_hist[r0.y], 1);
    atomicAdd(&g_hist[r0.z], 1);
    atomicAdd(&g_hist[r0.w], 1);
    atomicAdd(&g_hist[r1.x], 1);
    atomicAdd(&g_hist[r1.y], 1);
    atomicAdd(&g_hist[r1.z], 1);
    atomicAdd(&g_hist[r1.w], 1);
}

// -------------------------------------------------------------------------
// Kernel 3: single-block exclusive scan -> row_ptr + cursor.
// -------------------------------------------------------------------------
__global__ void lgcn_scan()
{
    const int T = 1024;
    const int CHUNK = (N_NODES + T - 1) / T;   // 147
    __shared__ int s_part[T];

    int t   = threadIdx.x;
    int beg = t * CHUNK;
    int end = min(beg + CHUNK, N_NODES);

    int sum = 0;
    for (int i = beg; i < end; i++) sum += g_hist[i];
    s_part[t] = sum;
    __syncthreads();

    for (int off = 1; off < T; off <<= 1) {
        int v = (t >= off) ? s_part[t - off] : 0;
        __syncthreads();
        s_part[t] += v;
        __syncthreads();
    }

    int run = s_part[t] - sum;
    for (int i = beg; i < end; i++) {
        g_rowptr[i] = run;
        g_cursor[i] = run;
        run += g_hist[i];
    }
    if (t == 0) g_rowptr[N_NODES] = NUM_EDGES;
}

// -------------------------------------------------------------------------
// Kernel 4: scatter edges into row-sorted interleaved array, 8 edges/thread
// (8 independent ATOMG round-trips in flight per thread).
// -------------------------------------------------------------------------
__global__ void lgcn_scatter(const float* __restrict__ edge_vals,
                             const int*   __restrict__ edge_row,
                             const int*   __restrict__ edge_col)
{
    int i = blockIdx.x * blockDim.x + threadIdx.x;
    if (i >= NUM_EDGES / 8) return;
    int4   r0 = ((const int4*)edge_row)[i * 2];
    int4   r1 = ((const int4*)edge_row)[i * 2 + 1];
    int4   c0 = ((const int4*)edge_col)[i * 2];
    int4   c1 = ((const int4*)edge_col)[i * 2 + 1];
    float4 v0 = ((const float4*)edge_vals)[i * 2];
    float4 v1 = ((const float4*)edge_vals)[i * 2 + 1];

    int p0 = atomicAdd(&g_cursor[r0.x], 1);
    int p1 = atomicAdd(&g_cursor[r0.y], 1);
    int p2 = atomicAdd(&g_cursor[r0.z], 1);
    int p3 = atomicAdd(&g_cursor[r0.w], 1);
    int p4 = atomicAdd(&g_cursor[r1.x], 1);
    int p5 = atomicAdd(&g_cursor[r1.y], 1);
    int p6 = atomicAdd(&g_cursor[r1.z], 1);
    int p7 = atomicAdd(&g_cursor[r1.w], 1);

    g_edges[p0] = make_int2(c0.x, __float_as_int(v0.x));
    g_edges[p1] = make_int2(c0.y, __float_as_int(v0.y));
    g_edges[p2] = make_int2(c0.z, __float_as_int(v0.z));
    g_edges[p3] = make_int2(c0.w, __float_as_int(v0.w));
    g_edges[p4] = make_int2(c1.x, __float_as_int(v1.x));
    g_edges[p5] = make_int2(c1.y, __float_as_int(v1.y));
    g_edges[p6] = make_int2(c1.z, __float_as_int(v1.z));
    g_edges[p7] = make_int2(c1.w, __float_as_int(v1.w));
}

// -------------------------------------------------------------------------
// Kernel 5: warp-per-node CSR gather.  Lanes hold float4 (16 lanes = 64
// dims); the two half-warps process TWO edges per iteration (j, j+1),
// doubling per-warp MLP.  shfl_xor(16) folds the half accumulators.
// MODE 0: layer1, virtual concat input, out = emb + acc.
// MODE 1: out += acc.   MODE 2: out = (out + acc) * 0.25.
// -------------------------------------------------------------------------
template<int MODE>
__global__ void __launch_bounds__(256)
lgcn_gather(const float* __restrict__ cur,
            const float* __restrict__ user_emb,
            const float* __restrict__ item_emb,
            float*       __restrict__ nxt,
            float*       __restrict__ out)
{
    __shared__ int2 s_edges[8][32];
    const int wslot = threadIdx.x >> 5;
    const int lane  = threadIdx.x & 31;
    const int half  = lane >> 4;       // which edge of the pair
    const int dlane = lane & 15;       // dim group (float4)
    const int node  = blockIdx.x * 8 + wslot;
    if (node >= N_NODES) return;

    const int start = g_rowptr[node];
    const int end   = g_rowptr[node + 1];

    float4 acc = make_float4(0.f, 0.f, 0.f, 0.f);

    for (int base = start; base < end; base += 32) {
        int idx = base + lane;
        if (idx < end) s_edges[wslot][lane] = g_edges[idx];
        __syncwarp();
        const int n = min(32, end - base);
        #pragma unroll 8
        for (int j = 0; j < n; j += 2) {
            const int jj = j + half;
            int2 cv = (jj < n) ? s_edges[wslot][jj] : make_int2(0, 0);
            float vj = __int_as_float(cv.y);
            const float4* src;
            if (MODE == 0) {
                const float4* us = (const float4*)user_emb + (size_t)cv.x * (DIM / 4);
                const float4* is = (const float4*)item_emb
                                   + (size_t)(cv.x - NUM_USERS) * (DIM / 4);
                src = (cv.x < NUM_USERS) ? us : is;   // branchless SEL
            } else {
                src = (const float4*)cur + (size_t)cv.x * (DIM / 4);
            }
            float4 x = __ldcg(src + dlane);
            acc.x += vj * x.x;
            acc.y += vj * x.y;
            acc.z += vj * x.z;
            acc.w += vj * x.w;
        }
        __syncwarp();
    }

    // Fold the two half-warp accumulators.
    acc.x += __shfl_xor_sync(0xffffffffu, acc.x, 16);
    acc.y += __shfl_xor_sync(0xffffffffu, acc.y, 16);
    acc.z += __shfl_xor_sync(0xffffffffu, acc.z, 16);
    acc.w += __shfl_xor_sync(0xffffffffu, acc.w, 16);

    if (half == 0) {
        float4* o = (float4*)(out + (size_t)node * DIM);
        if (MODE == 0) {
            const float4* e = (node < NUM_USERS)
                ? (const float4*)user_emb + (size_t)node * (DIM / 4)
                : (const float4*)item_emb + (size_t)(node - NUM_USERS) * (DIM / 4);
            float4 ev = e[dlane];
            o[dlane] = make_float4(ev.x + acc.x, ev.y + acc.y,
                                   ev.z + acc.z, ev.w + acc.w);
            ((float4*)(nxt + (size_t)node * DIM))[dlane] = acc;
        } else if (MODE == 1) {
            float4 a = o[dlane];
            a.x += acc.x; a.y += acc.y; a.z += acc.z; a.w += acc.w;
            o[dlane] = a;
            ((float4*)(nxt + (size_t)node * DIM))[dlane] = acc;
        } else {
            float4 a = o[dlane];
            a.x = (a.x + acc.x) * 0.25f;
            a.y = (a.y + acc.y) * 0.25f;
            a.z = (a.z + acc.z) * 0.25f;
            a.w = (a.w + acc.w) * 0.25f;
            o[dlane] = a;
        }
    }
}

// -------------------------------------------------------------------------
// Launch: 7 kernels, graph-capturable, no sync, no alloc.
// -------------------------------------------------------------------------
extern "C" void kernel_launch(void* const* d_in, const int* in_sizes, int n_in,
                              void* d_out, int out_size)
{
    const float* user_emb  = (const float*)d_in[0];
    const float* item_emb  = (const float*)d_in[1];
    const float* edge_vals = (const float*)d_in[2];
    const int*   edge_row  = (const int*)d_in[3];
    const int*   edge_col  = (const int*)d_in[4];
    float* out = (float*)d_out;

    float *bufA, *bufB;
    cudaGetSymbolAddress((void**)&bufA, g_bufA);
    cudaGetSymbolAddress((void**)&bufB, g_bufB);

    const int zero_grid = (N_NODES + 255) / 256;
    const int e8_grid   = (NUM_EDGES / 8 + 255) / 256;
    const int gather_grid = (N_NODES + 7) / 8;   // 8 warps/block

    // Build CSR (re-done every replay: deterministic, no cached state).
    lgcn_zero_hist<<<zero_grid, 256>>>();
    lgcn_hist<<<e8_grid, 256>>>(edge_row);
    lgcn_scan<<<1, 1024>>>();
    lgcn_scatter<<<e8_grid, 256>>>(edge_vals, edge_row, edge_col);

    // 3 propagation layers, accumulation fused.
    lgcn_gather<0><<<gather_grid, 256>>>(nullptr, user_emb, item_emb, bufB, out);
    lgcn_gather<1><<<gather_grid, 256>>>(bufB,    user_emb, item_emb, bufA, out);
    lgcn_gather<2><<<gather_grid, 256>>>(bufA,    user_emb, item_emb, nullptr, out);
}